// round 2
// baseline (speedup 1.0000x reference)
#include <cuda_runtime.h>

// Problem dims
#define BB    4
#define TT    2048
#define DM    1024
#define DKV   512
#define CHUNK 128
#define NC    (TT / CHUNK)   // 16

// GEMM tiling
#define BM  64
#define BN  64
#define BKT 16

// ---------------------------------------------------------------------------
// Scratch (static device arrays; no allocation allowed in kernel_launch)
// ---------------------------------------------------------------------------
__device__ float g_Q[BB * TT * DKV];                      // 16 MB
__device__ float g_K[BB * TT * DKV];                      // 16 MB
__device__ float g_V[BB * TT * DKV];                      // 16 MB
__device__ float g_Y[BB * TT * DKV];                      // 16 MB
__device__ float g_S[(long)BB * NC * DKV * DKV];          // 64 MB (chunk states -> exclusive prefix)
__device__ float g_P[BB * NC * CHUNK * CHUNK];            // 4 MB (masked intra-chunk scores)

// ---------------------------------------------------------------------------
// NT GEMM: C[m,n] = sum_k A[m,k] * B[n,k]   (both K-major / row-major over K)
// Optional strict-lower mask (c >= r -> 0), used for intra-chunk scores.
// blockIdx.z selects a batch/chunk slice via strides sA/sB/sC.
// ---------------------------------------------------------------------------
__global__ __launch_bounds__(256)
void gemm_nt(const float* __restrict__ Ab, const float* __restrict__ Bb,
             float* __restrict__ Cb, int K, int lda, int ldb, int ldc,
             long sA, long sB, long sC, int mask)
{
    const float* A = Ab + (long)blockIdx.z * sA;
    const float* B = Bb + (long)blockIdx.z * sB;
    float*       C = Cb + (long)blockIdx.z * sC;

    __shared__ float As[BKT][BM + 4];
    __shared__ float Bs[BKT][BN + 4];

    const int bm  = blockIdx.x * BM;
    const int bn  = blockIdx.y * BN;
    const int tid = threadIdx.x;
    const int tx  = tid & 15;
    const int ty  = tid >> 4;

    // transpose-load indices: each thread loads a float4 along K from one row
    const int lrow = tid >> 2;        // 0..63
    const int lk   = (tid & 3) << 2;  // 0,4,8,12

    const float* Aptr = A + (long)(bm + lrow) * lda + lk;
    const float* Bptr = B + (long)(bn + lrow) * ldb + lk;

    float acc[4][4] = {};

    for (int k0 = 0; k0 < K; k0 += BKT) {
        float4 av = *(const float4*)(Aptr + k0);
        float4 bv = *(const float4*)(Bptr + k0);
        As[lk + 0][lrow] = av.x; As[lk + 1][lrow] = av.y;
        As[lk + 2][lrow] = av.z; As[lk + 3][lrow] = av.w;
        Bs[lk + 0][lrow] = bv.x; Bs[lk + 1][lrow] = bv.y;
        Bs[lk + 2][lrow] = bv.z; Bs[lk + 3][lrow] = bv.w;
        __syncthreads();
        #pragma unroll
        for (int k = 0; k < BKT; k++) {
            float4 a4 = *(const float4*)&As[k][ty * 4];
            float4 b4 = *(const float4*)&Bs[k][tx * 4];
            float ar[4] = {a4.x, a4.y, a4.z, a4.w};
            float br[4] = {b4.x, b4.y, b4.z, b4.w};
            #pragma unroll
            for (int i = 0; i < 4; i++)
                #pragma unroll
                for (int j = 0; j < 4; j++)
                    acc[i][j] += ar[i] * br[j];
        }
        __syncthreads();
    }

    #pragma unroll
    for (int i = 0; i < 4; i++) {
        int r = bm + ty * 4 + i;
        #pragma unroll
        for (int j = 0; j < 4; j++) {
            int c = bn + tx * 4 + j;
            float v = acc[i][j];
            if (mask && c >= r) v = 0.0f;   // strict lower: keep s < t only
            C[(long)r * ldc + c] = v;
        }
    }
}

// ---------------------------------------------------------------------------
// TN GEMM: C[m,n] = sum_k A[k,m] * B[k,n]   (chunk state S = K^T V)
// ---------------------------------------------------------------------------
__global__ __launch_bounds__(256)
void gemm_tn(const float* __restrict__ Ab, const float* __restrict__ Bb,
             float* __restrict__ Cb, int K, int lda, int ldb, int ldc,
             long sA, long sB, long sC)
{
    const float* A = Ab + (long)blockIdx.z * sA;
    const float* B = Bb + (long)blockIdx.z * sB;
    float*       C = Cb + (long)blockIdx.z * sC;

    __shared__ float As[BKT][BM];
    __shared__ float Bs[BKT][BN];

    const int bm  = blockIdx.x * BM;
    const int bn  = blockIdx.y * BN;
    const int tid = threadIdx.x;
    const int tx  = tid & 15;
    const int ty  = tid >> 4;

    // direct-load indices: A and B are already [k][col]-major
    const int lk = tid >> 4;          // 0..15
    const int lc = (tid & 15) << 2;   // 0..60

    float acc[4][4] = {};

    for (int k0 = 0; k0 < K; k0 += BKT) {
        float4 av = *(const float4*)&A[(long)(k0 + lk) * lda + bm + lc];
        float4 bv = *(const float4*)&B[(long)(k0 + lk) * ldb + bn + lc];
        *(float4*)&As[lk][lc] = av;
        *(float4*)&Bs[lk][lc] = bv;
        __syncthreads();
        #pragma unroll
        for (int k = 0; k < BKT; k++) {
            float4 a4 = *(const float4*)&As[k][ty * 4];
            float4 b4 = *(const float4*)&Bs[k][tx * 4];
            float ar[4] = {a4.x, a4.y, a4.z, a4.w};
            float br[4] = {b4.x, b4.y, b4.z, b4.w};
            #pragma unroll
            for (int i = 0; i < 4; i++)
                #pragma unroll
                for (int j = 0; j < 4; j++)
                    acc[i][j] += ar[i] * br[j];
        }
        __syncthreads();
    }

    #pragma unroll
    for (int i = 0; i < 4; i++)
        #pragma unroll
        for (int j = 0; j < 4; j++)
            C[(long)(bm + ty * 4 + i) * ldc + bn + tx * 4 + j] = acc[i][j];
}

// ---------------------------------------------------------------------------
// Exclusive prefix over chunk dim: S[b,c] <- sum_{c'<c} S[b,c']
// One thread per (b, i, j) element; coalesced along i*DKV+j.
// ---------------------------------------------------------------------------
__global__ __launch_bounds__(256)
void prefix_kernel()
{
    long idx = (long)blockIdx.x * blockDim.x + threadIdx.x;  // over BB*DKV*DKV
    int  b   = (int)(idx / ((long)DKV * DKV));
    long ij  = idx % ((long)DKV * DKV);
    float acc = 0.0f;
    #pragma unroll
    for (int c = 0; c < NC; c++) {
        long off = ((long)(b * NC + c)) * DKV * DKV + ij;
        float s  = g_S[off];
        g_S[off] = acc;
        acc += s;
    }
}

// ---------------------------------------------------------------------------
// Y kernel: Y_c = P_c * V_c + Q_c * M_c   (two NN GEMM phases fused)
// z = b*NC + c. Tile grid: (CHUNK/BM, DKV/BN, BB*NC).
// ---------------------------------------------------------------------------
__global__ __launch_bounds__(256)
void y_kernel()
{
    const int z = blockIdx.z;
    const float* P   = g_P + (long)z * CHUNK * CHUNK;
    const float* V   = g_V + (long)z * CHUNK * DKV;
    const float* Q   = g_Q + (long)z * CHUNK * DKV;
    const float* Mst = g_S + (long)z * DKV * DKV;   // exclusive prefix = state before chunk
    float*       Y   = g_Y + (long)z * CHUNK * DKV;

    __shared__ float As[BKT][BM + 4];
    __shared__ float Bs[BKT][BN];

    const int bm  = blockIdx.x * BM;
    const int bn  = blockIdx.y * BN;
    const int tid = threadIdx.x;
    const int tx  = tid & 15;
    const int ty  = tid >> 4;

    const int lrow = tid >> 2;        // A transpose-load
    const int lka  = (tid & 3) << 2;
    const int lkb  = tid >> 4;        // B direct-load
    const int lnb  = (tid & 15) << 2;

    float acc[4][4] = {};

    // -------- phase 1: P (128x128, lda=CHUNK) x V (128x512, ldb=DKV) --------
    for (int k0 = 0; k0 < CHUNK; k0 += BKT) {
        float4 av = *(const float4*)&P[(long)(bm + lrow) * CHUNK + k0 + lka];
        float4 bv = *(const float4*)&V[(long)(k0 + lkb) * DKV + bn + lnb];
        As[lka + 0][lrow] = av.x; As[lka + 1][lrow] = av.y;
        As[lka + 2][lrow] = av.z; As[lka + 3][lrow] = av.w;
        *(float4*)&Bs[lkb][lnb] = bv;
        __syncthreads();
        #pragma unroll
        for (int k = 0; k < BKT; k++) {
            float4 a4 = *(const float4*)&As[k][ty * 4];
            float4 b4 = *(const float4*)&Bs[k][tx * 4];
            float ar[4] = {a4.x, a4.y, a4.z, a4.w};
            float br[4] = {b4.x, b4.y, b4.z, b4.w};
            #pragma unroll
            for (int i = 0; i < 4; i++)
                #pragma unroll
                for (int j = 0; j < 4; j++)
                    acc[i][j] += ar[i] * br[j];
        }
        __syncthreads();
    }

    // -------- phase 2: Q (128x512, lda=DKV) x M (512x512, ldb=DKV) ----------
    for (int k0 = 0; k0 < DKV; k0 += BKT) {
        float4 av = *(const float4*)&Q[(long)(bm + lrow) * DKV + k0 + lka];
        float4 bv = *(const float4*)&Mst[(long)(k0 + lkb) * DKV + bn + lnb];
        As[lka + 0][lrow] = av.x; As[lka + 1][lrow] = av.y;
        As[lka + 2][lrow] = av.z; As[lka + 3][lrow] = av.w;
        *(float4*)&Bs[lkb][lnb] = bv;
        __syncthreads();
        #pragma unroll
        for (int k = 0; k < BKT; k++) {
            float4 a4 = *(const float4*)&As[k][ty * 4];
            float4 b4 = *(const float4*)&Bs[k][tx * 4];
            float ar[4] = {a4.x, a4.y, a4.z, a4.w};
            float br[4] = {b4.x, b4.y, b4.z, b4.w};
            #pragma unroll
            for (int i = 0; i < 4; i++)
                #pragma unroll
                for (int j = 0; j < 4; j++)
                    acc[i][j] += ar[i] * br[j];
        }
        __syncthreads();
    }

    #pragma unroll
    for (int i = 0; i < 4; i++)
        #pragma unroll
        for (int j = 0; j < 4; j++)
            Y[(long)(bm + ty * 4 + i) * DKV + bn + tx * 4 + j] = acc[i][j];
}

// ---------------------------------------------------------------------------
// Launch
// ---------------------------------------------------------------------------
extern "C" void kernel_launch(void* const* d_in, const int* in_sizes, int n_in,
                              void* d_out, int out_size)
{
    const float* x  = (const float*)d_in[0];   // [B,T,DM]
    const float* Wq = (const float*)d_in[1];   // [DKV,DM]
    const float* Wk = (const float*)d_in[2];   // [DKV,DM]
    const float* Wv = (const float*)d_in[3];   // [DKV,DM]
    const float* Wo = (const float*)d_in[4];   // [DM,DKV]
    float* out = (float*)d_out;                // [B,T,DM]

    float* Q = nullptr; float* K = nullptr; float* V = nullptr;
    float* Y = nullptr; float* S = nullptr; float* P = nullptr;
    cudaGetSymbolAddress((void**)&Q, g_Q);
    cudaGetSymbolAddress((void**)&K, g_K);
    cudaGetSymbolAddress((void**)&V, g_V);
    cudaGetSymbolAddress((void**)&Y, g_Y);
    cudaGetSymbolAddress((void**)&S, g_S);
    cudaGetSymbolAddress((void**)&P, g_P);

    const int M = BB * TT;  // 8192

    // 1) Projections: Q/K/V = x @ W^T   (NT, M=8192, N=512, K=1024)
    {
        dim3 grid(M / BM, DKV / BN, 1);
        gemm_nt<<<grid, 256>>>(x, Wq, Q, DM, DM, DM, DKV, 0, 0, 0, 0);
        gemm_nt<<<grid, 256>>>(x, Wk, K, DM, DM, DM, DKV, 0, 0, 0, 0);
        gemm_nt<<<grid, 256>>>(x, Wv, V, DM, DM, DM, DKV, 0, 0, 0, 0);
    }

    // 2) Chunk states: S_c = K_c^T V_c   (TN, 512x512xK=128, per (b,chunk))
    {
        dim3 grid(DKV / BM, DKV / BN, BB * NC);
        gemm_tn<<<grid, 256>>>(K, V, S, CHUNK, DKV, DKV, DKV,
                               (long)CHUNK * DKV, (long)CHUNK * DKV,
                               (long)DKV * DKV);
    }

    // 3) Exclusive prefix over chunks -> M_c in-place in g_S
    {
        long n = (long)BB * DKV * DKV;
        prefix_kernel<<<(int)(n / 256), 256>>>();
    }

    // 4) Intra-chunk scores: P_c = strict_tril(Q_c K_c^T)  (NT, 128x128xK=512)
    {
        dim3 grid(CHUNK / BM, CHUNK / BN, BB * NC);
        gemm_nt<<<grid, 256>>>(Q, K, P, DKV, DKV, DKV, CHUNK,
                               (long)CHUNK * DKV, (long)CHUNK * DKV,
                               (long)CHUNK * CHUNK, 1);
    }

    // 5) Y_c = P_c V_c + Q_c M_c
    {
        dim3 grid(CHUNK / BM, DKV / BN, BB * NC);
        y_kernel<<<grid, 256>>>();
    }

    // 6) out = Y @ Wo^T   (NT, M=8192, N=1024, K=512)
    {
        dim3 grid(M / BM, DM / BN, 1);
        gemm_nt<<<grid, 256>>>(Y, Wo, out, DKV, DKV, DKV, DM, 0, 0, 0, 0);
    }
}

// round 5
// speedup vs baseline: 1.5133x; 1.5133x over previous
#include <cuda_runtime.h>
#include <cuda_bf16.h>
#include <cstdint>

// Problem dims
#define BB    4
#define TT    2048
#define DM    1024
#define DKV   512
#define CHUNK 128
#define NC    (TT / CHUNK)   // 16

// FFMA GEMM tiling (steps 2,5)
#define BM  64
#define BN  64
#define BKT 16

// ---------------------------------------------------------------------------
// Scratch
// ---------------------------------------------------------------------------
__device__ float g_Q[BB * TT * DKV];
__device__ float g_K[BB * TT * DKV];
__device__ float g_V[BB * TT * DKV];
__device__ float g_Y[BB * TT * DKV];
__device__ float g_S[(long)BB * NC * DKV * DKV];
__device__ float g_P[BB * NC * CHUNK * CHUNK];

__device__ __nv_bfloat16 g_xh[BB * TT * DM];
__device__ __nv_bfloat16 g_xl[BB * TT * DM];
__device__ __nv_bfloat16 g_Wh[3 * DKV * DM];    // Wq|Wk|Wv stacked [1536,1024]
__device__ __nv_bfloat16 g_Wl[3 * DKV * DM];
__device__ __nv_bfloat16 g_Woh[DM * DKV];
__device__ __nv_bfloat16 g_Wol[DM * DKV];
__device__ __nv_bfloat16 g_Yh[BB * TT * DKV];
__device__ __nv_bfloat16 g_Yl[BB * TT * DKV];
__device__ __nv_bfloat16 g_Qh[BB * TT * DKV];
__device__ __nv_bfloat16 g_Ql[BB * TT * DKV];
__device__ __nv_bfloat16 g_Kh[BB * TT * DKV];
__device__ __nv_bfloat16 g_Kl[BB * TT * DKV];

// ---------------------------------------------------------------------------
// Helpers (sm_100 base ISA only: mma.sync + ldmatrix + cp.async)
// ---------------------------------------------------------------------------
__device__ __forceinline__ uint32_t smem_u32(const void* p) {
    uint32_t a;
    asm("{ .reg .u64 t; cvta.to.shared.u64 t, %1; cvt.u32.u64 %0, t; }" : "=r"(a) : "l"(p));
    return a;
}

#define CPASYNC16(s, g) \
    asm volatile("cp.async.cg.shared.global [%0], [%1], 16;" :: "r"(s), "l"(g))
#define CPCOMMIT() asm volatile("cp.async.commit_group;" ::: "memory")
#define CPWAIT1()  asm volatile("cp.async.wait_group 1;" ::: "memory")
#define CPWAIT0()  asm volatile("cp.async.wait_group 0;" ::: "memory")

#define LDSM4(r0, r1, r2, r3, a) \
    asm volatile("ldmatrix.sync.aligned.m8n8.x4.shared.b16 {%0,%1,%2,%3}, [%4];" \
                 : "=r"(r0), "=r"(r1), "=r"(r2), "=r"(r3) : "r"(a))

#define MMA16816(d, a, b) \
    asm volatile("mma.sync.aligned.m16n8k16.row.col.f32.bf16.bf16.f32 " \
                 "{%0,%1,%2,%3},{%4,%5,%6,%7},{%8,%9},{%0,%1,%2,%3};" \
                 : "+f"((d)[0]), "+f"((d)[1]), "+f"((d)[2]), "+f"((d)[3]) \
                 : "r"((a)[0]), "r"((a)[1]), "r"((a)[2]), "r"((a)[3]), \
                   "r"((b)[0]), "r"((b)[1]))

// SMEM geometry: rows of 32 bf16 padded to 40 (80B) -> conflict-free ldmatrix
#define MROW_B 80                 // bytes per smem row
#define MATB   (128 * MROW_B)     // 10240 B per matrix tile (128 x 32 bf16)
#define STGB   (4 * MATB)         // Ah | Al | Bh | Bl
#define SMEMB  (2 * STGB)         // double buffered: 81920 B

// ---------------------------------------------------------------------------
// Tensor-core NT GEMM via mma.sync, bf16x3 emulation of fp32.
// C[m,n] = sum_k A[m,k]*B[n,k]. Tiles: CTA 128x128, warp 64x32, K-chunk 32.
// Optional strict-lower mask (c >= r -> 0). Batched via blockIdx.z strides.
// Output split into up to 3 buffers of nsplit columns each (QKV fusion).
// ---------------------------------------------------------------------------
__global__ __launch_bounds__(256)
void gemm_mma_nt(const __nv_bfloat16* __restrict__ Ah_, const __nv_bfloat16* __restrict__ Al_,
                 const __nv_bfloat16* __restrict__ Bh_, const __nv_bfloat16* __restrict__ Bl_,
                 float* C0, float* C1, float* C2,
                 int K, int lda, int ldb, int ldc, int nsplit,
                 long sA, long sB, long sC, int mask)
{
    extern __shared__ char smem[];
    const uint32_t sb = smem_u32(smem);
    const int tid = threadIdx.x;
    const int L   = tid & 31;
    const int w   = tid >> 5;
    const int wm  = w >> 2;       // 0..1
    const int wn  = w & 3;        // 0..3

    const int bm  = blockIdx.x * 128;
    const int bnG = blockIdx.y * 128;
    const int z   = blockIdx.z;
    const __nv_bfloat16* Ah = Ah_ + (long)z * sA;
    const __nv_bfloat16* Al = Al_ + (long)z * sA;
    const __nv_bfloat16* Bh = Bh_ + (long)z * sB;
    const __nv_bfloat16* Bl = Bl_ + (long)z * sB;
    const int buf  = bnG / nsplit;
    const int ncol = bnG % nsplit;
    float* C = ((buf == 0) ? C0 : (buf == 1) ? C1 : C2) + (long)z * sC;

    // loader indices: 256 threads cover 128 rows x 4 col-chunks x 4 matrices
    const int lrow = tid & 127;
    const int lc0  = tid >> 7;            // 0/1

    float acc[4][4][4];
    #pragma unroll
    for (int i = 0; i < 4; i++)
        #pragma unroll
        for (int j = 0; j < 4; j++)
            #pragma unroll
            for (int q = 0; q < 4; q++) acc[i][j][q] = 0.0f;

#define LOAD_STAGE(stg, k0) do {                                               \
    uint32_t sdst = sb + (uint32_t)(stg) * STGB + (uint32_t)lrow * MROW_B;     \
    const __nv_bfloat16* aR = Ah + (long)(bm + lrow) * lda + (k0);             \
    const __nv_bfloat16* lR = Al + (long)(bm + lrow) * lda + (k0);             \
    const __nv_bfloat16* bR = Bh + (long)(bnG + lrow) * ldb + (k0);            \
    const __nv_bfloat16* mR = Bl + (long)(bnG + lrow) * ldb + (k0);            \
    _Pragma("unroll")                                                          \
    for (int i2 = 0; i2 < 2; i2++) {                                           \
        int c16 = lc0 + i2 * 2;                                                \
        CPASYNC16(sdst + 0 * MATB + c16 * 16, aR + c16 * 8);                   \
        CPASYNC16(sdst + 1 * MATB + c16 * 16, lR + c16 * 8);                   \
        CPASYNC16(sdst + 2 * MATB + c16 * 16, bR + c16 * 8);                   \
        CPASYNC16(sdst + 3 * MATB + c16 * 16, mR + c16 * 8);                   \
    }                                                                          \
} while (0)

#define COMPUTE_STAGE(stg) do {                                                \
    const uint32_t s0 = sb + (uint32_t)(stg) * STGB;                           \
    _Pragma("unroll")                                                          \
    for (int kk = 0; kk < 2; kk++) {                                           \
        uint32_t a_h[4][4], a_l[4][4], b_h[4][2], b_l[4][2];                   \
        const int arow  = wm * 64 + (L & 7) + ((L >> 3) & 1) * 8;              \
        const int acolB = kk * 32 + ((L >> 4) & 1) * 16;                       \
        _Pragma("unroll")                                                      \
        for (int mt = 0; mt < 4; mt++) {                                       \
            uint32_t ad = s0 + (uint32_t)(arow + mt * 16) * MROW_B + acolB;    \
            LDSM4(a_h[mt][0], a_h[mt][1], a_h[mt][2], a_h[mt][3], ad);         \
            LDSM4(a_l[mt][0], a_l[mt][1], a_l[mt][2], a_l[mt][3], ad + MATB);  \
        }                                                                      \
        const int brow  = wn * 32 + (L & 7) + ((L >> 4) & 1) * 8;              \
        const int bcolB = kk * 32 + ((L >> 3) & 1) * 16;                       \
        _Pragma("unroll")                                                      \
        for (int p = 0; p < 2; p++) {                                          \
            uint32_t bd = s0 + 2 * MATB + (uint32_t)(brow + p * 16) * MROW_B + bcolB; \
            uint32_t r0, r1, r2, r3;                                           \
            LDSM4(r0, r1, r2, r3, bd);                                         \
            b_h[2 * p][0] = r0; b_h[2 * p][1] = r1;                            \
            b_h[2 * p + 1][0] = r2; b_h[2 * p + 1][1] = r3;                    \
            LDSM4(r0, r1, r2, r3, bd + MATB);                                  \
            b_l[2 * p][0] = r0; b_l[2 * p][1] = r1;                            \
            b_l[2 * p + 1][0] = r2; b_l[2 * p + 1][1] = r3;                    \
        }                                                                      \
        _Pragma("unroll")                                                      \
        for (int mt = 0; mt < 4; mt++)                                         \
            _Pragma("unroll")                                                  \
            for (int nt = 0; nt < 4; nt++) {                                   \
                MMA16816(acc[mt][nt], a_h[mt], b_h[nt]);                       \
                MMA16816(acc[mt][nt], a_h[mt], b_l[nt]);                       \
                MMA16816(acc[mt][nt], a_l[mt], b_h[nt]);                       \
            }                                                                  \
    }                                                                          \
} while (0)

    const int iters = K >> 5;   // K-chunks of 32
    LOAD_STAGE(0, 0);
    CPCOMMIT();
    for (int it = 0; it < iters; it++) {
        if (it + 1 < iters) {
            LOAD_STAGE((it + 1) & 1, (it + 1) * 32);
            CPCOMMIT();
            CPWAIT1();
        } else {
            CPWAIT0();
        }
        __syncthreads();
        COMPUTE_STAGE(it & 1);
        __syncthreads();
    }

    // Epilogue: direct stores (8B per quad element-pair)
    #pragma unroll
    for (int mt = 0; mt < 4; mt++) {
        #pragma unroll
        for (int nt = 0; nt < 4; nt++) {
            int rr = bm + wm * 64 + mt * 16 + (L >> 2);
            int cc = ncol + wn * 32 + nt * 8 + (L & 3) * 2;
            float d0 = acc[mt][nt][0], d1 = acc[mt][nt][1];
            float d2 = acc[mt][nt][2], d3 = acc[mt][nt][3];
            if (mask) {
                if (cc     >= rr)     d0 = 0.0f;
                if (cc + 1 >= rr)     d1 = 0.0f;
                if (cc     >= rr + 8) d2 = 0.0f;
                if (cc + 1 >= rr + 8) d3 = 0.0f;
            }
            float2 v01 = make_float2(d0, d1);
            float2 v23 = make_float2(d2, d3);
            *(float2*)&C[(long)rr * ldc + cc]       = v01;
            *(float2*)&C[(long)(rr + 8) * ldc + cc] = v23;
        }
    }
#undef LOAD_STAGE
#undef COMPUTE_STAGE
}

// ---------------------------------------------------------------------------
// fp32 -> bf16 hi/lo split
// ---------------------------------------------------------------------------
__global__ __launch_bounds__(256)
void cvt_hilo(const float* __restrict__ s, __nv_bfloat16* __restrict__ h,
              __nv_bfloat16* __restrict__ l, long n)
{
    long i = (long)blockIdx.x * 256 + threadIdx.x;
    if (i < n) {
        float v = s[i];
        __nv_bfloat16 hb = __float2bfloat16(v);
        h[i] = hb;
        l[i] = __float2bfloat16(v - __bfloat162float(hb));
    }
}

// ---------------------------------------------------------------------------
// FFMA kernels (steps 2,3,5 — unchanged from the 1400us baseline)
// ---------------------------------------------------------------------------
__global__ __launch_bounds__(256)
void gemm_tn(const float* __restrict__ Ab, const float* __restrict__ Bb,
             float* __restrict__ Cb, int K, int lda, int ldb, int ldc,
             long sA, long sB, long sC)
{
    const float* A = Ab + (long)blockIdx.z * sA;
    const float* B = Bb + (long)blockIdx.z * sB;
    float*       C = Cb + (long)blockIdx.z * sC;

    __shared__ float As[BKT][BM];
    __shared__ float Bs[BKT][BN];

    const int bm  = blockIdx.x * BM;
    const int bn  = blockIdx.y * BN;
    const int tid = threadIdx.x;
    const int tx  = tid & 15;
    const int ty  = tid >> 4;
    const int lk = tid >> 4;
    const int lc = (tid & 15) << 2;

    float acc[4][4] = {};
    for (int k0 = 0; k0 < K; k0 += BKT) {
        float4 av = *(const float4*)&A[(long)(k0 + lk) * lda + bm + lc];
        float4 bv = *(const float4*)&B[(long)(k0 + lk) * ldb + bn + lc];
        *(float4*)&As[lk][lc] = av;
        *(float4*)&Bs[lk][lc] = bv;
        __syncthreads();
        #pragma unroll
        for (int k = 0; k < BKT; k++) {
            float4 a4 = *(const float4*)&As[k][ty * 4];
            float4 b4 = *(const float4*)&Bs[k][tx * 4];
            float ar[4] = {a4.x, a4.y, a4.z, a4.w};
            float br[4] = {b4.x, b4.y, b4.z, b4.w};
            #pragma unroll
            for (int i = 0; i < 4; i++)
                #pragma unroll
                for (int j = 0; j < 4; j++)
                    acc[i][j] += ar[i] * br[j];
        }
        __syncthreads();
    }
    #pragma unroll
    for (int i = 0; i < 4; i++)
        #pragma unroll
        for (int j = 0; j < 4; j++)
            C[(long)(bm + ty * 4 + i) * ldc + bn + tx * 4 + j] = acc[i][j];
}

__global__ __launch_bounds__(256)
void prefix_kernel()
{
    long idx = (long)blockIdx.x * blockDim.x + threadIdx.x;
    int  b   = (int)(idx / ((long)DKV * DKV));
    long ij  = idx % ((long)DKV * DKV);
    float acc = 0.0f;
    #pragma unroll
    for (int c = 0; c < NC; c++) {
        long off = ((long)(b * NC + c)) * DKV * DKV + ij;
        float s  = g_S[off];
        g_S[off] = acc;
        acc += s;
    }
}

__global__ __launch_bounds__(256)
void y_kernel()
{
    const int z = blockIdx.z;
    const float* P   = g_P + (long)z * CHUNK * CHUNK;
    const float* V   = g_V + (long)z * CHUNK * DKV;
    const float* Q   = g_Q + (long)z * CHUNK * DKV;
    const float* Mst = g_S + (long)z * DKV * DKV;
    float*       Y   = g_Y + (long)z * CHUNK * DKV;

    __shared__ float As[BKT][BM + 4];
    __shared__ float Bs[BKT][BN];

    const int bm  = blockIdx.x * BM;
    const int bn  = blockIdx.y * BN;
    const int tid = threadIdx.x;
    const int tx  = tid & 15;
    const int ty  = tid >> 4;
    const int lrow = tid >> 2;
    const int lka  = (tid & 3) << 2;
    const int lkb  = tid >> 4;
    const int lnb  = (tid & 15) << 2;

    float acc[4][4] = {};
    for (int k0 = 0; k0 < CHUNK; k0 += BKT) {
        float4 av = *(const float4*)&P[(long)(bm + lrow) * CHUNK + k0 + lka];
        float4 bv = *(const float4*)&V[(long)(k0 + lkb) * DKV + bn + lnb];
        As[lka + 0][lrow] = av.x; As[lka + 1][lrow] = av.y;
        As[lka + 2][lrow] = av.z; As[lka + 3][lrow] = av.w;
        *(float4*)&Bs[lkb][lnb] = bv;
        __syncthreads();
        #pragma unroll
        for (int k = 0; k < BKT; k++) {
            float4 a4 = *(const float4*)&As[k][ty * 4];
            float4 b4 = *(const float4*)&Bs[k][tx * 4];
            float ar[4] = {a4.x, a4.y, a4.z, a4.w};
            float br[4] = {b4.x, b4.y, b4.z, b4.w};
            #pragma unroll
            for (int i = 0; i < 4; i++)
                #pragma unroll
                for (int j = 0; j < 4; j++)
                    acc[i][j] += ar[i] * br[j];
        }
        __syncthreads();
    }
    for (int k0 = 0; k0 < DKV; k0 += BKT) {
        float4 av = *(const float4*)&Q[(long)(bm + lrow) * DKV + k0 + lka];
        float4 bv = *(const float4*)&Mst[(long)(k0 + lkb) * DKV + bn + lnb];
        As[lka + 0][lrow] = av.x; As[lka + 1][lrow] = av.y;
        As[lka + 2][lrow] = av.z; As[lka + 3][lrow] = av.w;
        *(float4*)&Bs[lkb][lnb] = bv;
        __syncthreads();
        #pragma unroll
        for (int k = 0; k < BKT; k++) {
            float4 a4 = *(const float4*)&As[k][ty * 4];
            float4 b4 = *(const float4*)&Bs[k][tx * 4];
            float ar[4] = {a4.x, a4.y, a4.z, a4.w};
            float br[4] = {b4.x, b4.y, b4.z, b4.w};
            #pragma unroll
            for (int i = 0; i < 4; i++)
                #pragma unroll
                for (int j = 0; j < 4; j++)
                    acc[i][j] += ar[i] * br[j];
        }
        __syncthreads();
    }
    #pragma unroll
    for (int i = 0; i < 4; i++)
        #pragma unroll
        for (int j = 0; j < 4; j++)
            Y[(long)(bm + ty * 4 + i) * DKV + bn + tx * 4 + j] = acc[i][j];
}

// ---------------------------------------------------------------------------
// Launch
// ---------------------------------------------------------------------------
extern "C" void kernel_launch(void* const* d_in, const int* in_sizes, int n_in,
                              void* d_out, int out_size)
{
    const float* x  = (const float*)d_in[0];
    const float* Wq = (const float*)d_in[1];
    const float* Wk = (const float*)d_in[2];
    const float* Wv = (const float*)d_in[3];
    const float* Wo = (const float*)d_in[4];
    float* out = (float*)d_out;

    float *Q, *K, *V, *Y, *S, *P;
    __nv_bfloat16 *xh, *xl, *Wh, *Wl, *Woh, *Wol, *Yh, *Yl, *Qh, *Ql, *Kh, *Kl;
    cudaGetSymbolAddress((void**)&Q, g_Q);
    cudaGetSymbolAddress((void**)&K, g_K);
    cudaGetSymbolAddress((void**)&V, g_V);
    cudaGetSymbolAddress((void**)&Y, g_Y);
    cudaGetSymbolAddress((void**)&S, g_S);
    cudaGetSymbolAddress((void**)&P, g_P);
    cudaGetSymbolAddress((void**)&xh, g_xh);
    cudaGetSymbolAddress((void**)&xl, g_xl);
    cudaGetSymbolAddress((void**)&Wh, g_Wh);
    cudaGetSymbolAddress((void**)&Wl, g_Wl);
    cudaGetSymbolAddress((void**)&Woh, g_Woh);
    cudaGetSymbolAddress((void**)&Wol, g_Wol);
    cudaGetSymbolAddress((void**)&Yh, g_Yh);
    cudaGetSymbolAddress((void**)&Yl, g_Yl);
    cudaGetSymbolAddress((void**)&Qh, g_Qh);
    cudaGetSymbolAddress((void**)&Ql, g_Ql);
    cudaGetSymbolAddress((void**)&Kh, g_Kh);
    cudaGetSymbolAddress((void**)&Kl, g_Kl);

    cudaFuncSetAttribute(gemm_mma_nt, cudaFuncAttributeMaxDynamicSharedMemorySize,
                         SMEMB);

    const int M = BB * TT;  // 8192

    // 0) bf16 hi/lo conversions for inputs
    {
        long nx = (long)M * DM;
        cvt_hilo<<<(int)(nx / 256), 256>>>(x, xh, xl, nx);
        long nw = (long)DKV * DM;
        cvt_hilo<<<(int)(nw / 256), 256>>>(Wq, Wh, Wl, nw);
        cvt_hilo<<<(int)(nw / 256), 256>>>(Wk, Wh + nw, Wl + nw, nw);
        cvt_hilo<<<(int)(nw / 256), 256>>>(Wv, Wh + 2 * nw, Wl + 2 * nw, nw);
        long no = (long)DM * DKV;
        cvt_hilo<<<(int)(no / 256), 256>>>(Wo, Woh, Wol, no);
    }

    // 1) Q/K/V projections on tensor cores (fused, N = 1536 split into 3)
    {
        dim3 grid(M / 128, (3 * DKV) / 128, 1);
        gemm_mma_nt<<<grid, 256, SMEMB>>>(xh, xl, Wh, Wl, Q, K, V,
                                          DM, DM, DM, DKV, DKV,
                                          0, 0, 0, 0);
    }

    // 1b) Q,K -> bf16 hi/lo (for step 4 on tensor cores)
    {
        long nq = (long)M * DKV;
        cvt_hilo<<<(int)(nq / 256), 256>>>(Q, Qh, Ql, nq);
        cvt_hilo<<<(int)(nq / 256), 256>>>(K, Kh, Kl, nq);
    }

    // 2) Chunk states: S_c = K_c^T V_c  (FFMA TN)
    {
        dim3 grid(DKV / BM, DKV / BN, BB * NC);
        gemm_tn<<<grid, 256>>>(K, V, S, CHUNK, DKV, DKV, DKV,
                               (long)CHUNK * DKV, (long)CHUNK * DKV,
                               (long)DKV * DKV);
    }

    // 3) Exclusive prefix over chunks
    {
        long n = (long)BB * DKV * DKV;
        prefix_kernel<<<(int)(n / 256), 256>>>();
    }

    // 4) Intra-chunk scores: P_c = strict_tril(Q_c K_c^T) on tensor cores
    {
        dim3 grid(1, 1, BB * NC);
        gemm_mma_nt<<<grid, 256, SMEMB>>>(Qh, Ql, Kh, Kl, P, P, P,
                                          DKV, DKV, DKV, CHUNK, 1 << 30,
                                          (long)CHUNK * DKV, (long)CHUNK * DKV,
                                          (long)CHUNK * CHUNK, 1);
    }

    // 5) Y_c = P_c V_c + Q_c M_c  (FFMA)
    {
        dim3 grid(CHUNK / BM, DKV / BN, BB * NC);
        y_kernel<<<grid, 256>>>();
    }

    // 5b) Y -> bf16 hi/lo
    {
        long ny = (long)M * DKV;
        cvt_hilo<<<(int)(ny / 256), 256>>>(Y, Yh, Yl, ny);
    }

    // 6) out = Y @ Wo^T on tensor cores
    {
        dim3 grid(M / 128, DM / 128, 1);
        gemm_mma_nt<<<grid, 256, SMEMB>>>(Yh, Yl, Woh, Wol, out, out, out,
                                          DKV, DKV, DKV, DM, 1 << 30,
                                          0, 0, 0, 0);
    }
}

// round 7
// speedup vs baseline: 1.9880x; 1.3137x over previous
#include <cuda_runtime.h>
#include <cuda_bf16.h>
#include <cstdint>

// Problem dims
#define BB    4
#define TT    2048
#define DM    1024
#define DKV   512
#define CHUNK 128
#define NC    (TT / CHUNK)   // 16
#define MTOT  (BB * TT)      // 8192
#define NQKV  (3 * DKV)      // 1536

typedef __nv_bfloat16 bf16;

// ---------------------------------------------------------------------------
// Scratch
// ---------------------------------------------------------------------------
__device__ float g_S[(long)BB * NC * DKV * DKV];      // chunk states (fp32)

__device__ bf16 g_xh[MTOT * DM];
__device__ bf16 g_xl[MTOT * DM];
__device__ bf16 g_Wh[NQKV * DM];     // Wq|Wk|Wv stacked [1536,1024]
__device__ bf16 g_Wl[NQKV * DM];
__device__ bf16 g_Woh[DM * DKV];
__device__ bf16 g_Wol[DM * DKV];
__device__ bf16 g_QKVh[(long)MTOT * NQKV];   // Q|K|V cols, ld=1536
__device__ bf16 g_QKVl[(long)MTOT * NQKV];
__device__ bf16 g_Mh[(long)BB * NC * DKV * DKV];   // exclusive-prefix state
__device__ bf16 g_Ml[(long)BB * NC * DKV * DKV];
__device__ bf16 g_Ph[BB * NC * CHUNK * CHUNK];
__device__ bf16 g_Pl[BB * NC * CHUNK * CHUNK];
__device__ bf16 g_Yh[MTOT * DKV];
__device__ bf16 g_Yl[MTOT * DKV];

// ---------------------------------------------------------------------------
// Helpers (sm_100 base ISA: mma.sync + ldmatrix + cp.async)
// ---------------------------------------------------------------------------
__device__ __forceinline__ uint32_t smem_u32(const void* p) {
    uint32_t a;
    asm("{ .reg .u64 t; cvta.to.shared.u64 t, %1; cvt.u32.u64 %0, t; }" : "=r"(a) : "l"(p));
    return a;
}

#define CPASYNC16(s, g) \
    asm volatile("cp.async.cg.shared.global [%0], [%1], 16;" :: "r"(s), "l"(g))
#define CPCOMMIT() asm volatile("cp.async.commit_group;" ::: "memory")
#define CPWAIT1()  asm volatile("cp.async.wait_group 1;" ::: "memory")
#define CPWAIT0()  asm volatile("cp.async.wait_group 0;" ::: "memory")

#define LDSM4(r0, r1, r2, r3, a) \
    asm volatile("ldmatrix.sync.aligned.m8n8.x4.shared.b16 {%0,%1,%2,%3}, [%4];" \
                 : "=r"(r0), "=r"(r1), "=r"(r2), "=r"(r3) : "r"(a))
#define LDSM4T(r0, r1, r2, r3, a) \
    asm volatile("ldmatrix.sync.aligned.m8n8.x4.trans.shared.b16 {%0,%1,%2,%3}, [%4];" \
                 : "=r"(r0), "=r"(r1), "=r"(r2), "=r"(r3) : "r"(a))

#define MMA16816(d, a, b) \
    asm volatile("mma.sync.aligned.m16n8k16.row.col.f32.bf16.bf16.f32 " \
                 "{%0,%1,%2,%3},{%4,%5,%6,%7},{%8,%9},{%0,%1,%2,%3};" \
                 : "+f"((d)[0]), "+f"((d)[1]), "+f"((d)[2]), "+f"((d)[3]) \
                 : "r"((a)[0]), "r"((a)[1]), "r"((a)[2]), "r"((a)[3]), \
                   "r"((b)[0]), "r"((b)[1]))

__device__ __forceinline__ void split_hilo(float v, bf16& h, bf16& l) {
    h = __float2bfloat16(v);
    l = __float2bfloat16(v - __bfloat162float(h));
}

// ===========================================================================
// Kernel 1: NT GEMM (A[m,k], B[n,k]) — bf16x3, CTA 128x128, warp 64x32.
// outmode 0: fp32 to Cf.  outmode 1: bf16 hi/lo to Ch/Cl (after optional mask).
// ===========================================================================
#define NT_MROW 80                 // 32 bf16 padded to 80 B
#define NT_MAT  (128 * NT_MROW)    // 10240
#define NT_STG  (4 * NT_MAT)       // Ah|Al|Bh|Bl
#define NT_SMEM (2 * NT_STG)       // 81920

__global__ __launch_bounds__(256)
void gemm_mma_nt(const bf16* __restrict__ Ah_, const bf16* __restrict__ Al_,
                 const bf16* __restrict__ Bh_, const bf16* __restrict__ Bl_,
                 float* Cf, bf16* Ch, bf16* Cl,
                 int K, int lda, int ldb, int ldc,
                 long sA, long sB, long sC, int mask, int outmode)
{
    extern __shared__ char smem[];
    const uint32_t sb = smem_u32(smem);
    const int tid = threadIdx.x;
    const int L   = tid & 31;
    const int w   = tid >> 5;
    const int wm  = w >> 2;
    const int wn  = w & 3;

    const int bm  = blockIdx.x * 128;
    const int bn  = blockIdx.y * 128;
    const int z   = blockIdx.z;
    const bf16* Ah = Ah_ + (long)z * sA;
    const bf16* Al = Al_ + (long)z * sA;
    const bf16* Bh = Bh_ + (long)z * sB;
    const bf16* Bl = Bl_ + (long)z * sB;

    const int lrow = tid & 127;
    const int lc0  = tid >> 7;

    float acc[4][4][4];
    #pragma unroll
    for (int i = 0; i < 4; i++)
        #pragma unroll
        for (int j = 0; j < 4; j++) {
            acc[i][j][0] = 0.f; acc[i][j][1] = 0.f;
            acc[i][j][2] = 0.f; acc[i][j][3] = 0.f;
        }

    auto load_stage = [&](int stg, int k0) {
        uint32_t sdst = sb + (uint32_t)stg * NT_STG + (uint32_t)lrow * NT_MROW;
        const bf16* aR = Ah + (long)(bm + lrow) * lda + k0;
        const bf16* lR = Al + (long)(bm + lrow) * lda + k0;
        const bf16* bR = Bh + (long)(bn + lrow) * ldb + k0;
        const bf16* mR = Bl + (long)(bn + lrow) * ldb + k0;
        #pragma unroll
        for (int i2 = 0; i2 < 2; i2++) {
            int c16 = lc0 + i2 * 2;
            CPASYNC16(sdst + 0 * NT_MAT + c16 * 16, aR + c16 * 8);
            CPASYNC16(sdst + 1 * NT_MAT + c16 * 16, lR + c16 * 8);
            CPASYNC16(sdst + 2 * NT_MAT + c16 * 16, bR + c16 * 8);
            CPASYNC16(sdst + 3 * NT_MAT + c16 * 16, mR + c16 * 8);
        }
    };
    auto compute_stage = [&](int stg) {
        const uint32_t s0 = sb + (uint32_t)stg * NT_STG;
        #pragma unroll
        for (int kk = 0; kk < 2; kk++) {
            uint32_t a_h[4][4], a_l[4][4], b_h[4][2], b_l[4][2];
            const int arow  = wm * 64 + (L & 7) + ((L >> 3) & 1) * 8;
            const int acolB = kk * 32 + ((L >> 4) & 1) * 16;
            #pragma unroll
            for (int mt = 0; mt < 4; mt++) {
                uint32_t ad = s0 + (uint32_t)(arow + mt * 16) * NT_MROW + acolB;
                LDSM4(a_h[mt][0], a_h[mt][1], a_h[mt][2], a_h[mt][3], ad);
                LDSM4(a_l[mt][0], a_l[mt][1], a_l[mt][2], a_l[mt][3], ad + NT_MAT);
            }
            const int brow  = wn * 32 + (L & 7) + ((L >> 4) & 1) * 8;
            const int bcolB = kk * 32 + ((L >> 3) & 1) * 16;
            #pragma unroll
            for (int p = 0; p < 2; p++) {
                uint32_t bd = s0 + 2 * NT_MAT + (uint32_t)(brow + p * 16) * NT_MROW + bcolB;
                uint32_t r0, r1, r2, r3;
                LDSM4(r0, r1, r2, r3, bd);
                b_h[2 * p][0] = r0; b_h[2 * p][1] = r1;
                b_h[2 * p + 1][0] = r2; b_h[2 * p + 1][1] = r3;
                LDSM4(r0, r1, r2, r3, bd + NT_MAT);
                b_l[2 * p][0] = r0; b_l[2 * p][1] = r1;
                b_l[2 * p + 1][0] = r2; b_l[2 * p + 1][1] = r3;
            }
            #pragma unroll
            for (int mt = 0; mt < 4; mt++)
                #pragma unroll
                for (int nt = 0; nt < 4; nt++) {
                    MMA16816(acc[mt][nt], a_h[mt], b_h[nt]);
                    MMA16816(acc[mt][nt], a_h[mt], b_l[nt]);
                    MMA16816(acc[mt][nt], a_l[mt], b_h[nt]);
                }
        }
    };

    const int iters = K >> 5;
    load_stage(0, 0);
    CPCOMMIT();
    for (int it = 0; it < iters; it++) {
        if (it + 1 < iters) {
            load_stage((it + 1) & 1, (it + 1) * 32);
            CPCOMMIT();
            CPWAIT1();
        } else {
            CPWAIT0();
        }
        __syncthreads();
        compute_stage(it & 1);
        __syncthreads();
    }

    // Epilogue
    #pragma unroll
    for (int mt = 0; mt < 4; mt++) {
        #pragma unroll
        for (int nt = 0; nt < 4; nt++) {
            int rr = bm + wm * 64 + mt * 16 + (L >> 2);
            int cc = bn + wn * 32 + nt * 8 + (L & 3) * 2;
            float d0 = acc[mt][nt][0], d1 = acc[mt][nt][1];
            float d2 = acc[mt][nt][2], d3 = acc[mt][nt][3];
            if (mask) {
                if (cc     >= rr)     d0 = 0.0f;
                if (cc + 1 >= rr)     d1 = 0.0f;
                if (cc     >= rr + 8) d2 = 0.0f;
                if (cc + 1 >= rr + 8) d3 = 0.0f;
            }
            if (outmode == 0) {
                float* C = Cf + (long)z * sC;
                *(float2*)&C[(long)rr * ldc + cc]       = make_float2(d0, d1);
                *(float2*)&C[(long)(rr + 8) * ldc + cc] = make_float2(d2, d3);
            } else {
                bf16* CH = Ch + (long)z * sC;
                bf16* CL = Cl + (long)z * sC;
                __nv_bfloat162 h2, l2;
                split_hilo(d0, h2.x, l2.x); split_hilo(d1, h2.y, l2.y);
                *(__nv_bfloat162*)&CH[(long)rr * ldc + cc] = h2;
                *(__nv_bfloat162*)&CL[(long)rr * ldc + cc] = l2;
                split_hilo(d2, h2.x, l2.x); split_hilo(d3, h2.y, l2.y);
                *(__nv_bfloat162*)&CH[(long)(rr + 8) * ldc + cc] = h2;
                *(__nv_bfloat162*)&CL[(long)(rr + 8) * ldc + cc] = l2;
            }
        }
    }
}

// ===========================================================================
// Kernel 2: TN GEMM  S_c = K_c^T V_c  (A[k,m], B[k,n], k=time=128)
// Tiles [k32][col128] at 272 B pitch -> conflict-free trans ldmatrix.
// ===========================================================================
#define TN_ROW  272
#define TN_MAT  (32 * TN_ROW)     // 8704
#define TN_STG  (4 * TN_MAT)      // 34816
#define TN_SMEM (2 * TN_STG)      // 69632

__global__ __launch_bounds__(256)
void s_mma()
{
    extern __shared__ char smem[];
    const uint32_t sb = smem_u32(smem);
    const int tid = threadIdx.x;
    const int L   = tid & 31;
    const int w   = tid >> 5;
    const int wm  = w >> 2;
    const int wn  = w & 3;

    const int bm = blockIdx.x * 128;
    const int bn = blockIdx.y * 128;
    const int z  = blockIdx.z;
    const bf16* Ah = g_QKVh + DKV      + (long)z * CHUNK * NQKV;   // K
    const bf16* Al = g_QKVl + DKV      + (long)z * CHUNK * NQKV;
    const bf16* Bh = g_QKVh + 2 * DKV  + (long)z * CHUNK * NQKV;   // V
    const bf16* Bl = g_QKVl + 2 * DKV  + (long)z * CHUNK * NQKV;
    float* C = g_S + (long)z * DKV * DKV;

    float acc[4][4][4];
    #pragma unroll
    for (int i = 0; i < 4; i++)
        #pragma unroll
        for (int j = 0; j < 4; j++) {
            acc[i][j][0] = 0.f; acc[i][j][1] = 0.f;
            acc[i][j][2] = 0.f; acc[i][j][3] = 0.f;
        }

    auto load_stage = [&](int stg, int k0) {
        #pragma unroll
        for (int i = 0; i < 8; i++) {
            int lin = tid + i * 256;
            int mat = lin >> 9;
            int rem = lin & 511;
            int r   = rem >> 4;
            int c16 = rem & 15;
            const bf16* src = (mat == 0) ? Ah : (mat == 1) ? Al : (mat == 2) ? Bh : Bl;
            int colb = (mat < 2) ? bm : bn;
            src += (long)(k0 + r) * NQKV + colb + c16 * 8;
            uint32_t dst = sb + (uint32_t)stg * TN_STG + mat * TN_MAT
                         + (uint32_t)r * TN_ROW + c16 * 16;
            CPASYNC16(dst, src);
        }
    };
    auto compute_stage = [&](int stg) {
        const uint32_t s0 = sb + (uint32_t)stg * TN_STG;
        #pragma unroll
        for (int kk = 0; kk < 2; kk++) {
            uint32_t a_h[4][4], a_l[4][4], b_h[4][2], b_l[4][2];
            const int akrow = kk * 16 + (L & 7) + ((L >> 4) & 1) * 8;
            const int amcol = ((L >> 3) & 1) * 8;
            #pragma unroll
            for (int mt = 0; mt < 4; mt++) {
                uint32_t ad = s0 + (uint32_t)akrow * TN_ROW
                            + (uint32_t)(wm * 64 + mt * 16 + amcol) * 2;
                LDSM4T(a_h[mt][0], a_h[mt][1], a_h[mt][2], a_h[mt][3], ad);
                LDSM4T(a_l[mt][0], a_l[mt][1], a_l[mt][2], a_l[mt][3], ad + TN_MAT);
            }
            const int bkrow = kk * 16 + (L & 7) + ((L >> 3) & 1) * 8;
            const int bncol = ((L >> 4) & 1) * 8;
            #pragma unroll
            for (int p = 0; p < 2; p++) {
                uint32_t bd = s0 + 2 * TN_MAT + (uint32_t)bkrow * TN_ROW
                            + (uint32_t)(wn * 32 + p * 16 + bncol) * 2;
                uint32_t r0, r1, r2, r3;
                LDSM4T(r0, r1, r2, r3, bd);
                b_h[2 * p][0] = r0; b_h[2 * p][1] = r1;
                b_h[2 * p + 1][0] = r2; b_h[2 * p + 1][1] = r3;
                LDSM4T(r0, r1, r2, r3, bd + TN_MAT);
                b_l[2 * p][0] = r0; b_l[2 * p][1] = r1;
                b_l[2 * p + 1][0] = r2; b_l[2 * p + 1][1] = r3;
            }
            #pragma unroll
            for (int mt = 0; mt < 4; mt++)
                #pragma unroll
                for (int nt = 0; nt < 4; nt++) {
                    MMA16816(acc[mt][nt], a_h[mt], b_h[nt]);
                    MMA16816(acc[mt][nt], a_h[mt], b_l[nt]);
                    MMA16816(acc[mt][nt], a_l[mt], b_h[nt]);
                }
        }
    };

    const int iters = CHUNK >> 5;   // 4
    load_stage(0, 0);
    CPCOMMIT();
    for (int it = 0; it < iters; it++) {
        if (it + 1 < iters) {
            load_stage((it + 1) & 1, (it + 1) * 32);
            CPCOMMIT();
            CPWAIT1();
        } else {
            CPWAIT0();
        }
        __syncthreads();
        compute_stage(it & 1);
        __syncthreads();
    }

    #pragma unroll
    for (int mt = 0; mt < 4; mt++)
        #pragma unroll
        for (int nt = 0; nt < 4; nt++) {
            int rr = bm + wm * 64 + mt * 16 + (L >> 2);
            int cc = bn + wn * 32 + nt * 8 + (L & 3) * 2;
            *(float2*)&C[(long)rr * DKV + cc]       = make_float2(acc[mt][nt][0], acc[mt][nt][1]);
            *(float2*)&C[(long)(rr + 8) * DKV + cc] = make_float2(acc[mt][nt][2], acc[mt][nt][3]);
        }
}

// ===========================================================================
// Kernel 3: fused Y_c = P_c V_c + Q_c M_c   (NN x2: A normal, B trans)
// ===========================================================================
#define Y_AMAT  (128 * NT_MROW)    // 10240 (A: 128 x 32, 80 B pitch)
#define Y_BOFF  (2 * Y_AMAT)       // 20480
#define Y_BMAT  (32 * TN_ROW)      // 8704  (B: 32 x 128, 272 B pitch)
#define Y_STG   (Y_BOFF + 2 * Y_BMAT)  // 37888
#define Y_SMEM  (2 * Y_STG)        // 75776
#define Y_ITERS 20                 // 4 (P·V, K=128) + 16 (Q·M, K=512)

__global__ __launch_bounds__(256)
void y_mma()
{
    extern __shared__ char smem[];
    const uint32_t sb = smem_u32(smem);
    const int tid = threadIdx.x;
    const int L   = tid & 31;
    const int w   = tid >> 5;
    const int wm  = w >> 2;
    const int wn  = w & 3;

    const int bn = blockIdx.y * 128;
    const int z  = blockIdx.x;

    const bf16* Ph = g_Ph + (long)z * CHUNK * CHUNK;
    const bf16* Pl = g_Pl + (long)z * CHUNK * CHUNK;
    const bf16* Vh = g_QKVh + 2 * DKV + (long)z * CHUNK * NQKV;
    const bf16* Vl = g_QKVl + 2 * DKV + (long)z * CHUNK * NQKV;
    const bf16* Qh = g_QKVh + (long)z * CHUNK * NQKV;
    const bf16* Ql = g_QKVl + (long)z * CHUNK * NQKV;
    const bf16* Mh = g_Mh + (long)z * DKV * DKV;
    const bf16* Ml = g_Ml + (long)z * DKV * DKV;

    float acc[4][4][4];
    #pragma unroll
    for (int i = 0; i < 4; i++)
        #pragma unroll
        for (int j = 0; j < 4; j++) {
            acc[i][j][0] = 0.f; acc[i][j][1] = 0.f;
            acc[i][j][2] = 0.f; acc[i][j][3] = 0.f;
        }

    auto load_stage = [&](int stg, int it) {
        const int ph1 = (it < 4);
        const int k0  = ph1 ? it * 32 : (it - 4) * 32;
        const bf16* APh = ph1 ? Ph : Qh;
        const bf16* APl = ph1 ? Pl : Ql;
        const int   Alda = ph1 ? CHUNK : NQKV;
        const bf16* BPh = ph1 ? Vh : Mh;
        const bf16* BPl = ph1 ? Vl : Ml;
        const int   Bldb = ph1 ? NQKV : DKV;
        // A: 128 rows x 4 x16B x 2 mats = 1024 chunks
        #pragma unroll
        for (int i = 0; i < 4; i++) {
            int lin = tid + i * 256;
            int mat = lin >> 9;
            int rem = lin & 511;
            int r   = rem >> 2;
            int c16 = rem & 3;
            const bf16* src = (mat ? APl : APh) + (long)r * Alda + k0 + c16 * 8;
            uint32_t dst = sb + (uint32_t)stg * Y_STG + mat * Y_AMAT
                         + (uint32_t)r * NT_MROW + c16 * 16;
            CPASYNC16(dst, src);
        }
        // B: 32 rows x 16 x16B x 2 mats = 1024 chunks
        #pragma unroll
        for (int i = 0; i < 4; i++) {
            int lin = tid + i * 256;
            int mat = lin >> 9;
            int rem = lin & 511;
            int r   = rem >> 4;
            int c16 = rem & 15;
            const bf16* src = (mat ? BPl : BPh) + (long)(k0 + r) * Bldb + bn + c16 * 8;
            uint32_t dst = sb + (uint32_t)stg * Y_STG + Y_BOFF + mat * Y_BMAT
                         + (uint32_t)r * TN_ROW + c16 * 16;
            CPASYNC16(dst, src);
        }
    };
    auto compute_stage = [&](int stg) {
        const uint32_t s0 = sb + (uint32_t)stg * Y_STG;
        #pragma unroll
        for (int kk = 0; kk < 2; kk++) {
            uint32_t a_h[4][4], a_l[4][4], b_h[4][2], b_l[4][2];
            const int arow  = wm * 64 + (L & 7) + ((L >> 3) & 1) * 8;
            const int acolB = kk * 32 + ((L >> 4) & 1) * 16;
            #pragma unroll
            for (int mt = 0; mt < 4; mt++) {
                uint32_t ad = s0 + (uint32_t)(arow + mt * 16) * NT_MROW + acolB;
                LDSM4(a_h[mt][0], a_h[mt][1], a_h[mt][2], a_h[mt][3], ad);
                LDSM4(a_l[mt][0], a_l[mt][1], a_l[mt][2], a_l[mt][3], ad + Y_AMAT);
            }
            const int bkrow = kk * 16 + (L & 7) + ((L >> 3) & 1) * 8;
            const int bncol = ((L >> 4) & 1) * 8;
            #pragma unroll
            for (int p = 0; p < 2; p++) {
                uint32_t bd = s0 + Y_BOFF + (uint32_t)bkrow * TN_ROW
                            + (uint32_t)(wn * 32 + p * 16 + bncol) * 2;
                uint32_t r0, r1, r2, r3;
                LDSM4T(r0, r1, r2, r3, bd);
                b_h[2 * p][0] = r0; b_h[2 * p][1] = r1;
                b_h[2 * p + 1][0] = r2; b_h[2 * p + 1][1] = r3;
                LDSM4T(r0, r1, r2, r3, bd + Y_BMAT);
                b_l[2 * p][0] = r0; b_l[2 * p][1] = r1;
                b_l[2 * p + 1][0] = r2; b_l[2 * p + 1][1] = r3;
            }
            #pragma unroll
            for (int mt = 0; mt < 4; mt++)
                #pragma unroll
                for (int nt = 0; nt < 4; nt++) {
                    MMA16816(acc[mt][nt], a_h[mt], b_h[nt]);
                    MMA16816(acc[mt][nt], a_h[mt], b_l[nt]);
                    MMA16816(acc[mt][nt], a_l[mt], b_h[nt]);
                }
        }
    };

    load_stage(0, 0);
    CPCOMMIT();
    for (int it = 0; it < Y_ITERS; it++) {
        if (it + 1 < Y_ITERS) {
            load_stage((it + 1) & 1, it + 1);
            CPCOMMIT();
            CPWAIT1();
        } else {
            CPWAIT0();
        }
        __syncthreads();
        compute_stage(it & 1);
        __syncthreads();
    }

    bf16* YH = g_Yh + (long)z * CHUNK * DKV;
    bf16* YL = g_Yl + (long)z * CHUNK * DKV;
    #pragma unroll
    for (int mt = 0; mt < 4; mt++)
        #pragma unroll
        for (int nt = 0; nt < 4; nt++) {
            int rr = wm * 64 + mt * 16 + (L >> 2);
            int cc = bn + wn * 32 + nt * 8 + (L & 3) * 2;
            __nv_bfloat162 h2, l2;
            split_hilo(acc[mt][nt][0], h2.x, l2.x);
            split_hilo(acc[mt][nt][1], h2.y, l2.y);
            *(__nv_bfloat162*)&YH[(long)rr * DKV + cc] = h2;
            *(__nv_bfloat162*)&YL[(long)rr * DKV + cc] = l2;
            split_hilo(acc[mt][nt][2], h2.x, l2.x);
            split_hilo(acc[mt][nt][3], h2.y, l2.y);
            *(__nv_bfloat162*)&YH[(long)(rr + 8) * DKV + cc] = h2;
            *(__nv_bfloat162*)&YL[(long)(rr + 8) * DKV + cc] = l2;
        }
}

// ---------------------------------------------------------------------------
// Exclusive prefix over chunks: M_c = sum_{c'<c} S_{c'}  -> bf16 hi/lo
// ---------------------------------------------------------------------------
__global__ __launch_bounds__(256)
void prefix_kernel()
{
    long idx = (long)blockIdx.x * blockDim.x + threadIdx.x;
    int  b   = (int)(idx / ((long)DKV * DKV));
    long ij  = idx % ((long)DKV * DKV);
    float acc = 0.0f;
    #pragma unroll
    for (int c = 0; c < NC; c++) {
        long off = ((long)(b * NC + c)) * DKV * DKV + ij;
        float s  = g_S[off];
        bf16 hb, lb;
        split_hilo(acc, hb, lb);
        g_Mh[off] = hb;
        g_Ml[off] = lb;
        acc += s;
    }
}

// ---------------------------------------------------------------------------
// fp32 -> bf16 hi/lo split (inputs only)
// ---------------------------------------------------------------------------
__global__ __launch_bounds__(256)
void cvt_hilo(const float* __restrict__ s, bf16* __restrict__ h,
              bf16* __restrict__ l, long n)
{
    long i = (long)blockIdx.x * 256 + threadIdx.x;
    if (i < n) {
        bf16 hb, lb;
        split_hilo(s[i], hb, lb);
        h[i] = hb;
        l[i] = lb;
    }
}

// ---------------------------------------------------------------------------
// Launch
// ---------------------------------------------------------------------------
extern "C" void kernel_launch(void* const* d_in, const int* in_sizes, int n_in,
                              void* d_out, int out_size)
{
    const float* x  = (const float*)d_in[0];
    const float* Wq = (const float*)d_in[1];
    const float* Wk = (const float*)d_in[2];
    const float* Wv = (const float*)d_in[3];
    const float* Wo = (const float*)d_in[4];
    float* out = (float*)d_out;

    bf16 *xh, *xl, *Wh, *Wl, *Woh, *Wol, *QKVh, *QKVl, *Ph, *Pl, *Yh, *Yl;
    cudaGetSymbolAddress((void**)&xh, g_xh);
    cudaGetSymbolAddress((void**)&xl, g_xl);
    cudaGetSymbolAddress((void**)&Wh, g_Wh);
    cudaGetSymbolAddress((void**)&Wl, g_Wl);
    cudaGetSymbolAddress((void**)&Woh, g_Woh);
    cudaGetSymbolAddress((void**)&Wol, g_Wol);
    cudaGetSymbolAddress((void**)&QKVh, g_QKVh);
    cudaGetSymbolAddress((void**)&QKVl, g_QKVl);
    cudaGetSymbolAddress((void**)&Ph, g_Ph);
    cudaGetSymbolAddress((void**)&Pl, g_Pl);
    cudaGetSymbolAddress((void**)&Yh, g_Yh);
    cudaGetSymbolAddress((void**)&Yl, g_Yl);

    cudaFuncSetAttribute(gemm_mma_nt, cudaFuncAttributeMaxDynamicSharedMemorySize, NT_SMEM);
    cudaFuncSetAttribute(s_mma,       cudaFuncAttributeMaxDynamicSharedMemorySize, TN_SMEM);
    cudaFuncSetAttribute(y_mma,       cudaFuncAttributeMaxDynamicSharedMemorySize, Y_SMEM);

    // 0) input conversions
    {
        long nx = (long)MTOT * DM;
        cvt_hilo<<<(int)(nx / 256), 256>>>(x, xh, xl, nx);
        long nw = (long)DKV * DM;
        cvt_hilo<<<(int)(nw / 256), 256>>>(Wq, Wh, Wl, nw);
        cvt_hilo<<<(int)(nw / 256), 256>>>(Wk, Wh + nw, Wl + nw, nw);
        cvt_hilo<<<(int)(nw / 256), 256>>>(Wv, Wh + 2 * nw, Wl + 2 * nw, nw);
        long no = (long)DM * DKV;
        cvt_hilo<<<(int)(no / 256), 256>>>(Wo, Woh, Wol, no);
    }

    // 1) QKV projection -> unified bf16 hi/lo buffer [8192 x 1536]
    {
        dim3 grid(MTOT / 128, NQKV / 128, 1);
        gemm_mma_nt<<<grid, 256, NT_SMEM>>>(xh, xl, Wh, Wl,
                                            nullptr, QKVh, QKVl,
                                            DM, DM, DM, NQKV,
                                            0, 0, 0, 0, 1);
    }

    // 2) chunk states S_c = K_c^T V_c (fp32)
    {
        dim3 grid(DKV / 128, DKV / 128, BB * NC);
        s_mma<<<grid, 256, TN_SMEM>>>();
    }

    // 3) exclusive prefix -> M hi/lo
    {
        long n = (long)BB * DKV * DKV;
        prefix_kernel<<<(int)(n / 256), 256>>>();
    }

    // 4) P_c = strict_tril(Q_c K_c^T) -> bf16 hi/lo
    {
        dim3 grid(1, 1, BB * NC);
        gemm_mma_nt<<<grid, 256, NT_SMEM>>>(QKVh, QKVl, QKVh + DKV, QKVl + DKV,
                                            nullptr, Ph, Pl,
                                            DKV, NQKV, NQKV, CHUNK,
                                            (long)CHUNK * NQKV, (long)CHUNK * NQKV,
                                            (long)CHUNK * CHUNK, 1, 1);
    }

    // 5) Y_c = P_c V_c + Q_c M_c -> bf16 hi/lo
    {
        dim3 grid(BB * NC, DKV / 128, 1);
        y_mma<<<grid, 256, Y_SMEM>>>();
    }

    // 6) out = Y @ Wo^T (fp32)
    {
        dim3 grid(MTOT / 128, DM / 128, 1);
        gemm_mma_nt<<<grid, 256, NT_SMEM>>>(Yh, Yl, Woh, Wol,
                                            out, nullptr, nullptr,
                                            DKV, DKV, DKV, DM,
                                            0, 0, 0, 0, 0);
    }
}

// round 8
// speedup vs baseline: 2.0068x; 1.0094x over previous
#include <cuda_runtime.h>
#include <cuda_bf16.h>
#include <cstdint>

// Problem dims
#define BB    4
#define TT    2048
#define DM    1024
#define DKV   512
#define CHUNK 128
#define NC    (TT / CHUNK)   // 16
#define MTOT  (BB * TT)      // 8192
#define NQKV  (3 * DKV)      // 1536

typedef __nv_bfloat16 bf16;

// ---------------------------------------------------------------------------
// Scratch
// ---------------------------------------------------------------------------
__device__ float g_S[(long)BB * NC * DKV * DKV];      // chunk states (fp32)

__device__ bf16 g_xh[MTOT * DM];
__device__ bf16 g_xl[MTOT * DM];
__device__ bf16 g_Wh[NQKV * DM];     // Wq|Wk|Wv stacked [1536,1024]
__device__ bf16 g_Wl[NQKV * DM];
__device__ bf16 g_Woh[DM * DKV];
__device__ bf16 g_Wol[DM * DKV];
__device__ bf16 g_QKVh[(long)MTOT * NQKV];   // Q|K|V cols, ld=1536
__device__ bf16 g_QKVl[(long)MTOT * NQKV];
__device__ bf16 g_Mh[(long)BB * NC * DKV * DKV];   // exclusive-prefix state
__device__ bf16 g_Ml[(long)BB * NC * DKV * DKV];
__device__ bf16 g_Ph[BB * NC * CHUNK * CHUNK];
__device__ bf16 g_Pl[BB * NC * CHUNK * CHUNK];
__device__ bf16 g_Yh[MTOT * DKV];
__device__ bf16 g_Yl[MTOT * DKV];

// ---------------------------------------------------------------------------
// Helpers (sm_100 base ISA: mma.sync + ldmatrix + cp.async)
// ---------------------------------------------------------------------------
__device__ __forceinline__ uint32_t smem_u32(const void* p) {
    uint32_t a;
    asm("{ .reg .u64 t; cvta.to.shared.u64 t, %1; cvt.u32.u64 %0, t; }" : "=r"(a) : "l"(p));
    return a;
}

#define CPASYNC16(s, g) \
    asm volatile("cp.async.cg.shared.global [%0], [%1], 16;" :: "r"(s), "l"(g))
#define CPCOMMIT() asm volatile("cp.async.commit_group;" ::: "memory")
#define CPWAIT1()  asm volatile("cp.async.wait_group 1;" ::: "memory")
#define CPWAIT0()  asm volatile("cp.async.wait_group 0;" ::: "memory")

#define LDSM4(r0, r1, r2, r3, a) \
    asm volatile("ldmatrix.sync.aligned.m8n8.x4.shared.b16 {%0,%1,%2,%3}, [%4];" \
                 : "=r"(r0), "=r"(r1), "=r"(r2), "=r"(r3) : "r"(a))
#define LDSM4T(r0, r1, r2, r3, a) \
    asm volatile("ldmatrix.sync.aligned.m8n8.x4.trans.shared.b16 {%0,%1,%2,%3}, [%4];" \
                 : "=r"(r0), "=r"(r1), "=r"(r2), "=r"(r3) : "r"(a))

#define MMA16816(d, a, b) \
    asm volatile("mma.sync.aligned.m16n8k16.row.col.f32.bf16.bf16.f32 " \
                 "{%0,%1,%2,%3},{%4,%5,%6,%7},{%8,%9},{%0,%1,%2,%3};" \
                 : "+f"((d)[0]), "+f"((d)[1]), "+f"((d)[2]), "+f"((d)[3]) \
                 : "r"((a)[0]), "r"((a)[1]), "r"((a)[2]), "r"((a)[3]), \
                   "r"((b)[0]), "r"((b)[1]))

// Three-term emulated-fp32 MMA block, ordered for tensor-pipe pipelining:
// each term sweeps all 16 independent accumulators before re-touching one.
#define MMA_TERMS_4x4(acc, a_h, a_l, b_h, b_l) do {                    \
    _Pragma("unroll")                                                  \
    for (int mt = 0; mt < 4; mt++)                                     \
        _Pragma("unroll")                                              \
        for (int nt = 0; nt < 4; nt++)                                 \
            MMA16816(acc[mt][nt], a_h[mt], b_h[nt]);                   \
    _Pragma("unroll")                                                  \
    for (int mt = 0; mt < 4; mt++)                                     \
        _Pragma("unroll")                                              \
        for (int nt = 0; nt < 4; nt++)                                 \
            MMA16816(acc[mt][nt], a_h[mt], b_l[nt]);                   \
    _Pragma("unroll")                                                  \
    for (int mt = 0; mt < 4; mt++)                                     \
        _Pragma("unroll")                                              \
        for (int nt = 0; nt < 4; nt++)                                 \
            MMA16816(acc[mt][nt], a_l[mt], b_h[nt]);                   \
} while (0)

__device__ __forceinline__ void split_hilo(float v, bf16& h, bf16& l) {
    h = __float2bfloat16(v);
    l = __float2bfloat16(v - __bfloat162float(h));
}

// ===========================================================================
// Kernel 1: NT GEMM (A[m,k], B[n,k]) — bf16x3, CTA 128x128, warp 64x32.
// outmode 0: fp32 to Cf.  outmode 1: bf16 hi/lo to Ch/Cl (after optional mask).
// ===========================================================================
#define NT_MROW 80                 // 32 bf16 padded to 80 B
#define NT_MAT  (128 * NT_MROW)    // 10240
#define NT_STG  (4 * NT_MAT)       // Ah|Al|Bh|Bl
#define NT_SMEM (2 * NT_STG)       // 81920

__global__ __launch_bounds__(256)
void gemm_mma_nt(const bf16* __restrict__ Ah_, const bf16* __restrict__ Al_,
                 const bf16* __restrict__ Bh_, const bf16* __restrict__ Bl_,
                 float* Cf, bf16* Ch, bf16* Cl,
                 int K, int lda, int ldb, int ldc,
                 long sA, long sB, long sC, int mask, int outmode)
{
    extern __shared__ char smem[];
    const uint32_t sb = smem_u32(smem);
    const int tid = threadIdx.x;
    const int L   = tid & 31;
    const int w   = tid >> 5;
    const int wm  = w >> 2;
    const int wn  = w & 3;

    const int bm  = blockIdx.x * 128;
    const int bn  = blockIdx.y * 128;
    const int z   = blockIdx.z;
    const bf16* Ah = Ah_ + (long)z * sA;
    const bf16* Al = Al_ + (long)z * sA;
    const bf16* Bh = Bh_ + (long)z * sB;
    const bf16* Bl = Bl_ + (long)z * sB;

    const int lrow = tid & 127;
    const int lc0  = tid >> 7;

    float acc[4][4][4];
    #pragma unroll
    for (int i = 0; i < 4; i++)
        #pragma unroll
        for (int j = 0; j < 4; j++) {
            acc[i][j][0] = 0.f; acc[i][j][1] = 0.f;
            acc[i][j][2] = 0.f; acc[i][j][3] = 0.f;
        }

    auto load_stage = [&](int stg, int k0) {
        uint32_t sdst = sb + (uint32_t)stg * NT_STG + (uint32_t)lrow * NT_MROW;
        const bf16* aR = Ah + (long)(bm + lrow) * lda + k0;
        const bf16* lR = Al + (long)(bm + lrow) * lda + k0;
        const bf16* bR = Bh + (long)(bn + lrow) * ldb + k0;
        const bf16* mR = Bl + (long)(bn + lrow) * ldb + k0;
        #pragma unroll
        for (int i2 = 0; i2 < 2; i2++) {
            int c16 = lc0 + i2 * 2;
            CPASYNC16(sdst + 0 * NT_MAT + c16 * 16, aR + c16 * 8);
            CPASYNC16(sdst + 1 * NT_MAT + c16 * 16, lR + c16 * 8);
            CPASYNC16(sdst + 2 * NT_MAT + c16 * 16, bR + c16 * 8);
            CPASYNC16(sdst + 3 * NT_MAT + c16 * 16, mR + c16 * 8);
        }
    };
    auto compute_stage = [&](int stg) {
        const uint32_t s0 = sb + (uint32_t)stg * NT_STG;
        #pragma unroll
        for (int kk = 0; kk < 2; kk++) {
            uint32_t a_h[4][4], a_l[4][4], b_h[4][2], b_l[4][2];
            const int arow  = wm * 64 + (L & 7) + ((L >> 3) & 1) * 8;
            const int acolB = kk * 32 + ((L >> 4) & 1) * 16;
            #pragma unroll
            for (int mt = 0; mt < 4; mt++) {
                uint32_t ad = s0 + (uint32_t)(arow + mt * 16) * NT_MROW + acolB;
                LDSM4(a_h[mt][0], a_h[mt][1], a_h[mt][2], a_h[mt][3], ad);
                LDSM4(a_l[mt][0], a_l[mt][1], a_l[mt][2], a_l[mt][3], ad + NT_MAT);
            }
            const int brow  = wn * 32 + (L & 7) + ((L >> 4) & 1) * 8;
            const int bcolB = kk * 32 + ((L >> 3) & 1) * 16;
            #pragma unroll
            for (int p = 0; p < 2; p++) {
                uint32_t bd = s0 + 2 * NT_MAT + (uint32_t)(brow + p * 16) * NT_MROW + bcolB;
                uint32_t r0, r1, r2, r3;
                LDSM4(r0, r1, r2, r3, bd);
                b_h[2 * p][0] = r0; b_h[2 * p][1] = r1;
                b_h[2 * p + 1][0] = r2; b_h[2 * p + 1][1] = r3;
                LDSM4(r0, r1, r2, r3, bd + NT_MAT);
                b_l[2 * p][0] = r0; b_l[2 * p][1] = r1;
                b_l[2 * p + 1][0] = r2; b_l[2 * p + 1][1] = r3;
            }
            MMA_TERMS_4x4(acc, a_h, a_l, b_h, b_l);
        }
    };

    const int iters = K >> 5;
    load_stage(0, 0);
    CPCOMMIT();
    for (int it = 0; it < iters; it++) {
        if (it + 1 < iters) {
            load_stage((it + 1) & 1, (it + 1) * 32);
            CPCOMMIT();
            CPWAIT1();
        } else {
            CPWAIT0();
        }
        __syncthreads();
        compute_stage(it & 1);
        __syncthreads();
    }

    // Epilogue
    #pragma unroll
    for (int mt = 0; mt < 4; mt++) {
        #pragma unroll
        for (int nt = 0; nt < 4; nt++) {
            int rr = bm + wm * 64 + mt * 16 + (L >> 2);
            int cc = bn + wn * 32 + nt * 8 + (L & 3) * 2;
            float d0 = acc[mt][nt][0], d1 = acc[mt][nt][1];
            float d2 = acc[mt][nt][2], d3 = acc[mt][nt][3];
            if (mask) {
                if (cc     >= rr)     d0 = 0.0f;
                if (cc + 1 >= rr)     d1 = 0.0f;
                if (cc     >= rr + 8) d2 = 0.0f;
                if (cc + 1 >= rr + 8) d3 = 0.0f;
            }
            if (outmode == 0) {
                float* C = Cf + (long)z * sC;
                *(float2*)&C[(long)rr * ldc + cc]       = make_float2(d0, d1);
                *(float2*)&C[(long)(rr + 8) * ldc + cc] = make_float2(d2, d3);
            } else {
                bf16* CH = Ch + (long)z * sC;
                bf16* CL = Cl + (long)z * sC;
                __nv_bfloat162 h2, l2;
                split_hilo(d0, h2.x, l2.x); split_hilo(d1, h2.y, l2.y);
                *(__nv_bfloat162*)&CH[(long)rr * ldc + cc] = h2;
                *(__nv_bfloat162*)&CL[(long)rr * ldc + cc] = l2;
                split_hilo(d2, h2.x, l2.x); split_hilo(d3, h2.y, l2.y);
                *(__nv_bfloat162*)&CH[(long)(rr + 8) * ldc + cc] = h2;
                *(__nv_bfloat162*)&CL[(long)(rr + 8) * ldc + cc] = l2;
            }
        }
    }
}

// ===========================================================================
// Kernel 2: TN GEMM  S_c = K_c^T V_c  (A[k,m], B[k,n], k=time=128)
// Tiles [k32][col128] at 272 B pitch -> conflict-free trans ldmatrix.
// ===========================================================================
#define TN_ROW  272
#define TN_MAT  (32 * TN_ROW)     // 8704
#define TN_STG  (4 * TN_MAT)      // 34816
#define TN_SMEM (2 * TN_STG)      // 69632

__global__ __launch_bounds__(256)
void s_mma()
{
    extern __shared__ char smem[];
    const uint32_t sb = smem_u32(smem);
    const int tid = threadIdx.x;
    const int L   = tid & 31;
    const int w   = tid >> 5;
    const int wm  = w >> 2;
    const int wn  = w & 3;

    const int bm = blockIdx.x * 128;
    const int bn = blockIdx.y * 128;
    const int z  = blockIdx.z;
    const bf16* Ah = g_QKVh + DKV      + (long)z * CHUNK * NQKV;   // K
    const bf16* Al = g_QKVl + DKV      + (long)z * CHUNK * NQKV;
    const bf16* Bh = g_QKVh + 2 * DKV  + (long)z * CHUNK * NQKV;   // V
    const bf16* Bl = g_QKVl + 2 * DKV  + (long)z * CHUNK * NQKV;
    float* C = g_S + (long)z * DKV * DKV;

    float acc[4][4][4];
    #pragma unroll
    for (int i = 0; i < 4; i++)
        #pragma unroll
        for (int j = 0; j < 4; j++) {
            acc[i][j][0] = 0.f; acc[i][j][1] = 0.f;
            acc[i][j][2] = 0.f; acc[i][j][3] = 0.f;
        }

    auto load_stage = [&](int stg, int k0) {
        #pragma unroll
        for (int i = 0; i < 8; i++) {
            int lin = tid + i * 256;
            int mat = lin >> 9;
            int rem = lin & 511;
            int r   = rem >> 4;
            int c16 = rem & 15;
            const bf16* src = (mat == 0) ? Ah : (mat == 1) ? Al : (mat == 2) ? Bh : Bl;
            int colb = (mat < 2) ? bm : bn;
            src += (long)(k0 + r) * NQKV + colb + c16 * 8;
            uint32_t dst = sb + (uint32_t)stg * TN_STG + mat * TN_MAT
                         + (uint32_t)r * TN_ROW + c16 * 16;
            CPASYNC16(dst, src);
        }
    };
    auto compute_stage = [&](int stg) {
        const uint32_t s0 = sb + (uint32_t)stg * TN_STG;
        #pragma unroll
        for (int kk = 0; kk < 2; kk++) {
            uint32_t a_h[4][4], a_l[4][4], b_h[4][2], b_l[4][2];
            const int akrow = kk * 16 + (L & 7) + ((L >> 4) & 1) * 8;
            const int amcol = ((L >> 3) & 1) * 8;
            #pragma unroll
            for (int mt = 0; mt < 4; mt++) {
                uint32_t ad = s0 + (uint32_t)akrow * TN_ROW
                            + (uint32_t)(wm * 64 + mt * 16 + amcol) * 2;
                LDSM4T(a_h[mt][0], a_h[mt][1], a_h[mt][2], a_h[mt][3], ad);
                LDSM4T(a_l[mt][0], a_l[mt][1], a_l[mt][2], a_l[mt][3], ad + TN_MAT);
            }
            const int bkrow = kk * 16 + (L & 7) + ((L >> 3) & 1) * 8;
            const int bncol = ((L >> 4) & 1) * 8;
            #pragma unroll
            for (int p = 0; p < 2; p++) {
                uint32_t bd = s0 + 2 * TN_MAT + (uint32_t)bkrow * TN_ROW
                            + (uint32_t)(wn * 32 + p * 16 + bncol) * 2;
                uint32_t r0, r1, r2, r3;
                LDSM4T(r0, r1, r2, r3, bd);
                b_h[2 * p][0] = r0; b_h[2 * p][1] = r1;
                b_h[2 * p + 1][0] = r2; b_h[2 * p + 1][1] = r3;
                LDSM4T(r0, r1, r2, r3, bd + TN_MAT);
                b_l[2 * p][0] = r0; b_l[2 * p][1] = r1;
                b_l[2 * p + 1][0] = r2; b_l[2 * p + 1][1] = r3;
            }
            MMA_TERMS_4x4(acc, a_h, a_l, b_h, b_l);
        }
    };

    const int iters = CHUNK >> 5;   // 4
    load_stage(0, 0);
    CPCOMMIT();
    for (int it = 0; it < iters; it++) {
        if (it + 1 < iters) {
            load_stage((it + 1) & 1, (it + 1) * 32);
            CPCOMMIT();
            CPWAIT1();
        } else {
            CPWAIT0();
        }
        __syncthreads();
        compute_stage(it & 1);
        __syncthreads();
    }

    #pragma unroll
    for (int mt = 0; mt < 4; mt++)
        #pragma unroll
        for (int nt = 0; nt < 4; nt++) {
            int rr = bm + wm * 64 + mt * 16 + (L >> 2);
            int cc = bn + wn * 32 + nt * 8 + (L & 3) * 2;
            *(float2*)&C[(long)rr * DKV + cc]       = make_float2(acc[mt][nt][0], acc[mt][nt][1]);
            *(float2*)&C[(long)(rr + 8) * DKV + cc] = make_float2(acc[mt][nt][2], acc[mt][nt][3]);
        }
}

// ===========================================================================
// Kernel 3: fused Y_c = P_c V_c + Q_c M_c   (NN x2: A normal, B trans)
// ===========================================================================
#define Y_AMAT  (128 * NT_MROW)    // 10240 (A: 128 x 32, 80 B pitch)
#define Y_BOFF  (2 * Y_AMAT)       // 20480
#define Y_BMAT  (32 * TN_ROW)      // 8704  (B: 32 x 128, 272 B pitch)
#define Y_STG   (Y_BOFF + 2 * Y_BMAT)  // 37888
#define Y_SMEM  (2 * Y_STG)        // 75776
#define Y_ITERS 20                 // 4 (P·V, K=128) + 16 (Q·M, K=512)

__global__ __launch_bounds__(256)
void y_mma()
{
    extern __shared__ char smem[];
    const uint32_t sb = smem_u32(smem);
    const int tid = threadIdx.x;
    const int L   = tid & 31;
    const int w   = tid >> 5;
    const int wm  = w >> 2;
    const int wn  = w & 3;

    const int bn = blockIdx.y * 128;
    const int z  = blockIdx.x;

    const bf16* Ph = g_Ph + (long)z * CHUNK * CHUNK;
    const bf16* Pl = g_Pl + (long)z * CHUNK * CHUNK;
    const bf16* Vh = g_QKVh + 2 * DKV + (long)z * CHUNK * NQKV;
    const bf16* Vl = g_QKVl + 2 * DKV + (long)z * CHUNK * NQKV;
    const bf16* Qh = g_QKVh + (long)z * CHUNK * NQKV;
    const bf16* Ql = g_QKVl + (long)z * CHUNK * NQKV;
    const bf16* Mh = g_Mh + (long)z * DKV * DKV;
    const bf16* Ml = g_Ml + (long)z * DKV * DKV;

    float acc[4][4][4];
    #pragma unroll
    for (int i = 0; i < 4; i++)
        #pragma unroll
        for (int j = 0; j < 4; j++) {
            acc[i][j][0] = 0.f; acc[i][j][1] = 0.f;
            acc[i][j][2] = 0.f; acc[i][j][3] = 0.f;
        }

    auto load_stage = [&](int stg, int it) {
        const int ph1 = (it < 4);
        const int k0  = ph1 ? it * 32 : (it - 4) * 32;
        const bf16* APh = ph1 ? Ph : Qh;
        const bf16* APl = ph1 ? Pl : Ql;
        const int   Alda = ph1 ? CHUNK : NQKV;
        const bf16* BPh = ph1 ? Vh : Mh;
        const bf16* BPl = ph1 ? Vl : Ml;
        const int   Bldb = ph1 ? NQKV : DKV;
        // A: 128 rows x 4 x16B x 2 mats = 1024 chunks
        #pragma unroll
        for (int i = 0; i < 4; i++) {
            int lin = tid + i * 256;
            int mat = lin >> 9;
            int rem = lin & 511;
            int r   = rem >> 2;
            int c16 = rem & 3;
            const bf16* src = (mat ? APl : APh) + (long)r * Alda + k0 + c16 * 8;
            uint32_t dst = sb + (uint32_t)stg * Y_STG + mat * Y_AMAT
                         + (uint32_t)r * NT_MROW + c16 * 16;
            CPASYNC16(dst, src);
        }
        // B: 32 rows x 16 x16B x 2 mats = 1024 chunks
        #pragma unroll
        for (int i = 0; i < 4; i++) {
            int lin = tid + i * 256;
            int mat = lin >> 9;
            int rem = lin & 511;
            int r   = rem >> 4;
            int c16 = rem & 15;
            const bf16* src = (mat ? BPl : BPh) + (long)(k0 + r) * Bldb + bn + c16 * 8;
            uint32_t dst = sb + (uint32_t)stg * Y_STG + Y_BOFF + mat * Y_BMAT
                         + (uint32_t)r * TN_ROW + c16 * 16;
            CPASYNC16(dst, src);
        }
    };
    auto compute_stage = [&](int stg) {
        const uint32_t s0 = sb + (uint32_t)stg * Y_STG;
        #pragma unroll
        for (int kk = 0; kk < 2; kk++) {
            uint32_t a_h[4][4], a_l[4][4], b_h[4][2], b_l[4][2];
            const int arow  = wm * 64 + (L & 7) + ((L >> 3) & 1) * 8;
            const int acolB = kk * 32 + ((L >> 4) & 1) * 16;
            #pragma unroll
            for (int mt = 0; mt < 4; mt++) {
                uint32_t ad = s0 + (uint32_t)(arow + mt * 16) * NT_MROW + acolB;
                LDSM4(a_h[mt][0], a_h[mt][1], a_h[mt][2], a_h[mt][3], ad);
                LDSM4(a_l[mt][0], a_l[mt][1], a_l[mt][2], a_l[mt][3], ad + Y_AMAT);
            }
            const int bkrow = kk * 16 + (L & 7) + ((L >> 3) & 1) * 8;
            const int bncol = ((L >> 4) & 1) * 8;
            #pragma unroll
            for (int p = 0; p < 2; p++) {
                uint32_t bd = s0 + Y_BOFF + (uint32_t)bkrow * TN_ROW
                            + (uint32_t)(wn * 32 + p * 16 + bncol) * 2;
                uint32_t r0, r1, r2, r3;
                LDSM4T(r0, r1, r2, r3, bd);
                b_h[2 * p][0] = r0; b_h[2 * p][1] = r1;
                b_h[2 * p + 1][0] = r2; b_h[2 * p + 1][1] = r3;
                LDSM4T(r0, r1, r2, r3, bd + Y_BMAT);
                b_l[2 * p][0] = r0; b_l[2 * p][1] = r1;
                b_l[2 * p + 1][0] = r2; b_l[2 * p + 1][1] = r3;
            }
            MMA_TERMS_4x4(acc, a_h, a_l, b_h, b_l);
        }
    };

    load_stage(0, 0);
    CPCOMMIT();
    for (int it = 0; it < Y_ITERS; it++) {
        if (it + 1 < Y_ITERS) {
            load_stage((it + 1) & 1, it + 1);
            CPCOMMIT();
            CPWAIT1();
        } else {
            CPWAIT0();
        }
        __syncthreads();
        compute_stage(it & 1);
        __syncthreads();
    }

    bf16* YH = g_Yh + (long)z * CHUNK * DKV;
    bf16* YL = g_Yl + (long)z * CHUNK * DKV;
    #pragma unroll
    for (int mt = 0; mt < 4; mt++)
        #pragma unroll
        for (int nt = 0; nt < 4; nt++) {
            int rr = wm * 64 + mt * 16 + (L >> 2);
            int cc = bn + wn * 32 + nt * 8 + (L & 3) * 2;
            __nv_bfloat162 h2, l2;
            split_hilo(acc[mt][nt][0], h2.x, l2.x);
            split_hilo(acc[mt][nt][1], h2.y, l2.y);
            *(__nv_bfloat162*)&YH[(long)rr * DKV + cc] = h2;
            *(__nv_bfloat162*)&YL[(long)rr * DKV + cc] = l2;
            split_hilo(acc[mt][nt][2], h2.x, l2.x);
            split_hilo(acc[mt][nt][3], h2.y, l2.y);
            *(__nv_bfloat162*)&YH[(long)(rr + 8) * DKV + cc] = h2;
            *(__nv_bfloat162*)&YL[(long)(rr + 8) * DKV + cc] = l2;
        }
}

// ---------------------------------------------------------------------------
// Exclusive prefix over chunks: M_c = sum_{c'<c} S_{c'}  -> bf16 hi/lo
// ---------------------------------------------------------------------------
__global__ __launch_bounds__(256)
void prefix_kernel()
{
    long idx = (long)blockIdx.x * blockDim.x + threadIdx.x;
    int  b   = (int)(idx / ((long)DKV * DKV));
    long ij  = idx % ((long)DKV * DKV);
    float acc = 0.0f;
    #pragma unroll
    for (int c = 0; c < NC; c++) {
        long off = ((long)(b * NC + c)) * DKV * DKV + ij;
        float s  = g_S[off];
        bf16 hb, lb;
        split_hilo(acc, hb, lb);
        g_Mh[off] = hb;
        g_Ml[off] = lb;
        acc += s;
    }
}

// ---------------------------------------------------------------------------
// One fused input conversion kernel: x, Wq|Wk|Wv, Wo -> bf16 hi/lo
// ---------------------------------------------------------------------------
#define NX  ((long)MTOT * DM)        // 8388608
#define NW  ((long)DKV * DM)         // 524288
#define NO  ((long)DM * DKV)         // 524288
#define NCVT (NX + 3 * NW + NO)      // 10485760

__global__ __launch_bounds__(256)
void cvt_all(const float* __restrict__ x,  const float* __restrict__ wq,
             const float* __restrict__ wk, const float* __restrict__ wv,
             const float* __restrict__ wo)
{
    long i = (long)blockIdx.x * 256 + threadIdx.x;
    const float* s;
    bf16 *h, *l;
    long j;
    if (i < NX)                { s = x;  h = g_xh;  l = g_xl;  j = i; }
    else if (i < NX + NW)      { s = wq; h = g_Wh;  l = g_Wl;  j = i - NX; }
    else if (i < NX + 2 * NW)  { s = wk; h = g_Wh + NW;  l = g_Wl + NW;  j = i - NX - NW; }
    else if (i < NX + 3 * NW)  { s = wv; h = g_Wh + 2 * NW; l = g_Wl + 2 * NW; j = i - NX - 2 * NW; }
    else                       { s = wo; h = g_Woh; l = g_Wol; j = i - NX - 3 * NW; }
    bf16 hb, lb;
    split_hilo(s[j], hb, lb);
    h[j] = hb;
    l[j] = lb;
}

// ---------------------------------------------------------------------------
// Launch
// ---------------------------------------------------------------------------
extern "C" void kernel_launch(void* const* d_in, const int* in_sizes, int n_in,
                              void* d_out, int out_size)
{
    const float* x  = (const float*)d_in[0];
    const float* Wq = (const float*)d_in[1];
    const float* Wk = (const float*)d_in[2];
    const float* Wv = (const float*)d_in[3];
    const float* Wo = (const float*)d_in[4];
    float* out = (float*)d_out;

    bf16 *xh, *xl, *Wh, *Wl, *Woh, *Wol, *QKVh, *QKVl, *Ph, *Pl, *Yh, *Yl;
    cudaGetSymbolAddress((void**)&xh, g_xh);
    cudaGetSymbolAddress((void**)&xl, g_xl);
    cudaGetSymbolAddress((void**)&Wh, g_Wh);
    cudaGetSymbolAddress((void**)&Wl, g_Wl);
    cudaGetSymbolAddress((void**)&Woh, g_Woh);
    cudaGetSymbolAddress((void**)&Wol, g_Wol);
    cudaGetSymbolAddress((void**)&QKVh, g_QKVh);
    cudaGetSymbolAddress((void**)&QKVl, g_QKVl);
    cudaGetSymbolAddress((void**)&Ph, g_Ph);
    cudaGetSymbolAddress((void**)&Pl, g_Pl);
    cudaGetSymbolAddress((void**)&Yh, g_Yh);
    cudaGetSymbolAddress((void**)&Yl, g_Yl);

    cudaFuncSetAttribute(gemm_mma_nt, cudaFuncAttributeMaxDynamicSharedMemorySize, NT_SMEM);
    cudaFuncSetAttribute(s_mma,       cudaFuncAttributeMaxDynamicSharedMemorySize, TN_SMEM);
    cudaFuncSetAttribute(y_mma,       cudaFuncAttributeMaxDynamicSharedMemorySize, Y_SMEM);

    // 0) fused input conversions (1 launch)
    cvt_all<<<(int)(NCVT / 256), 256>>>(x, Wq, Wk, Wv, Wo);

    // 1) QKV projection -> unified bf16 hi/lo buffer [8192 x 1536]
    {
        dim3 grid(MTOT / 128, NQKV / 128, 1);
        gemm_mma_nt<<<grid, 256, NT_SMEM>>>(xh, xl, Wh, Wl,
                                            nullptr, QKVh, QKVl,
                                            DM, DM, DM, NQKV,
                                            0, 0, 0, 0, 1);
    }

    // 2) chunk states S_c = K_c^T V_c (fp32)
    {
        dim3 grid(DKV / 128, DKV / 128, BB * NC);
        s_mma<<<grid, 256, TN_SMEM>>>();
    }

    // 3) exclusive prefix -> M hi/lo
    {
        long n = (long)BB * DKV * DKV;
        prefix_kernel<<<(int)(n / 256), 256>>>();
    }

    // 4) P_c = strict_tril(Q_c K_c^T) -> bf16 hi/lo
    {
        dim3 grid(1, 1, BB * NC);
        gemm_mma_nt<<<grid, 256, NT_SMEM>>>(QKVh, QKVl, QKVh + DKV, QKVl + DKV,
                                            nullptr, Ph, Pl,
                                            DKV, NQKV, NQKV, CHUNK,
                                            (long)CHUNK * NQKV, (long)CHUNK * NQKV,
                                            (long)CHUNK * CHUNK, 1, 1);
    }

    // 5) Y_c = P_c V_c + Q_c M_c -> bf16 hi/lo
    {
        dim3 grid(BB * NC, DKV / 128, 1);
        y_mma<<<grid, 256, Y_SMEM>>>();
    }

    // 6) out = Y @ Wo^T (fp32)
    {
        dim3 grid(MTOT / 128, DM / 128, 1);
        gemm_mma_nt<<<grid, 256, NT_SMEM>>>(Yh, Yl, Woh, Wol,
                                            out, nullptr, nullptr,
                                            DKV, DKV, DKV, DM,
                                            0, 0, 0, 0, 0);
    }
}